// round 14
// baseline (speedup 1.0000x reference)
#include <cuda_runtime.h>
#include <cuda_fp16.h>
#include <cstdint>

#define B_     64
#define N_     256
#define INDIM  512
#define OUTDIM 512
#define KSLOT  8
#define DKDIM  64

// Scratch: HT fp16 [b][feature][m], Wt fp16 [out][in]
__device__ __half g_ht_h[(size_t)B_ * OUTDIM * N_];
__device__ __half g_wt_h[OUTDIM * INDIM];

// ---------------------------------------------------------------------------
__device__ __forceinline__ uint32_t h2(float x, float y) {
    __half2 t = __floats2half2_rn(x, y);      // .x = low halfword
    return *reinterpret_cast<uint32_t*>(&t);
}

__device__ __forceinline__ void mma_fp16(float c[4], const uint32_t a[4], const uint32_t b[2]) {
    asm volatile(
        "mma.sync.aligned.m16n8k16.row.col.f32.f16.f16.f32 "
        "{%0,%1,%2,%3}, {%4,%5,%6,%7}, {%8,%9}, {%0,%1,%2,%3};"
        : "+f"(c[0]), "+f"(c[1]), "+f"(c[2]), "+f"(c[3])
        : "r"(a[0]), "r"(a[1]), "r"(a[2]), "r"(a[3]), "r"(b[0]), "r"(b[1]));
}

__device__ __forceinline__ void ldm4(uint32_t& r0, uint32_t& r1, uint32_t& r2, uint32_t& r3,
                                     uint32_t addr) {
    asm volatile("ldmatrix.sync.aligned.m8n8.x4.shared.b16 {%0,%1,%2,%3}, [%4];"
                 : "=r"(r0), "=r"(r1), "=r"(r2), "=r"(r3) : "r"(addr));
}

__device__ __forceinline__ uint32_t smem_u32(const void* p) {
    uint32_t a;
    asm("{ .reg .u64 t; cvta.to.shared.u64 t, %1; cvt.u32.u64 %0, t; }" : "=r"(a) : "l"(p));
    return a;
}

#define CP16(dst_u32, src_ptr) \
    asm volatile("cp.async.cg.shared.global [%0], [%1], 16;" :: "r"(dst_u32), "l"(src_ptr))
#define CP_COMMIT() asm volatile("cp.async.commit_group;" ::: "memory")
#define CP_WAIT2()  asm volatile("cp.async.wait_group 2;" ::: "memory")

// Row = 32 fp16 k-elements = 16 uint32 + 4 pad -> PITCH 20 uint32 (80 B).
// ldmatrix phase: 8 rows x 16B, start banks 20r mod 32 = perfect permutation.
#define PITCH   20
// Stage geometry: A rows then B rows, all pitch-20.
#define S1_AROWS 128
#define S1_BROWS 128                          // f-tile = 128
#define S1_BUFSZ ((S1_AROWS + S1_BROWS) * PITCH)
#define S1_DYN   (4 * S1_BUFSZ * 4)           // 81920 B
#define S2_AROWS 128
#define S2_BROWS 64
#define S2_BUFSZ ((S2_AROWS + S2_BROWS) * PITCH)
#define S2_DYN   (4 * S2_BUFSZ * 4)           // 61440 B

// ---------------------------------------------------------------------------
// Kernel 0: Wt fp16  (Wt[n][k] = (half)W[k][n])
// ---------------------------------------------------------------------------
__global__ __launch_bounds__(256) void wt_kernel(const float* __restrict__ W,
                                                 __half* __restrict__ Wt) {
    __shared__ float t[32][33];
    const int bx = blockIdx.x * 32;   // out (n)
    const int by = blockIdx.y * 32;   // in  (k)
    #pragma unroll
    for (int i = 0; i < 4; i++)
        t[threadIdx.y + i * 8][threadIdx.x] = W[(size_t)(by + threadIdx.y + i * 8) * OUTDIM + bx + threadIdx.x];
    __syncthreads();
    #pragma unroll
    for (int i = 0; i < 4; i++)
        Wt[(size_t)(bx + threadIdx.y + i * 8) * INDIM + by + threadIdx.x] =
            __float2half_rn(t[threadIdx.x][threadIdx.y + i * 8]);
}

// ---------------------------------------------------------------------------
// Fragment compute over one resident stage (k=32 -> 2 k16 steps), ldmatrix.
// Warp tile 64(m) x 32(n). B rows start at AROWS (template arg).
// ---------------------------------------------------------------------------
template <int AROWS>
__device__ __forceinline__ void chunk_mma_ldm(
    uint32_t sbase, float c[4][4][4], int rowA0, int rowB0, int lane)
{
    const int lr = lane & 15;
    const int lc = lane >> 4;
    #pragma unroll
    for (int ks = 0; ks < 2; ks++) {
        const uint32_t segoff = (uint32_t)(ks * 2 + lc) * 16u;   // bytes
        uint32_t afr[4][4];
        #pragma unroll
        for (int mt = 0; mt < 4; mt++) {
            uint32_t addr = sbase + (uint32_t)(rowA0 + mt * 16 + lr) * (PITCH * 4) + segoff;
            ldm4(afr[mt][0], afr[mt][1], afr[mt][2], afr[mt][3], addr);
        }
        uint32_t bfr[4][2];
        #pragma unroll
        for (int p = 0; p < 2; p++) {
            uint32_t addr = sbase + (uint32_t)(AROWS + rowB0 + p * 16 + lr) * (PITCH * 4) + segoff;
            uint32_t r0, r1, r2, r3;
            ldm4(r0, r1, r2, r3, addr);
            bfr[2 * p][0] = r0; bfr[2 * p + 1][0] = r1;
            bfr[2 * p][1] = r2; bfr[2 * p + 1][1] = r3;
        }
        #pragma unroll
        for (int mt = 0; mt < 4; mt++)
            #pragma unroll
            for (int nt = 0; nt < 4; nt++)
                mma_fp16(c[mt][nt], afr[mt], bfr[nt]);
    }
}

// ---------------------------------------------------------------------------
// Stage 1: HT[b][f][m] = (half) relu( X @ W + bias )
// CTA 128(m) x 128(f), 8 warps (2 wr x 4 wc), warp tile 64x32. 16 k-chunks,
// 4-stage pipe. Grid (4, 128) — X L2 re-read cut from 8x to 4x.
// A(X fp32): LDG -> (next iter) cvt+STS ; B(Wt fp16): cp.async.
// ---------------------------------------------------------------------------
__global__ __launch_bounds__(256) void s1_linear_mma(
    const float* __restrict__ X, const __half* __restrict__ Wt,
    const float* __restrict__ bias, __half* __restrict__ HT)
{
    extern __shared__ uint32_t smu[];
    const uint32_t sb = smem_u32(smu);

    const int tid = threadIdx.x;
    const int warpId = tid >> 5, lid = tid & 31;
    const int gid = lid >> 2, tig = lid & 3;
    const int wr = warpId & 1;            // m: 2 warps * 64
    const int wc = warpId >> 1;           // f: 4 warps * 32
    const int mBase = blockIdx.y * 128;
    const int fBase = blockIdx.x * 128;

    float4 ar[4];

    auto ldgA = [&](int k0) {             // X: 128 rows x 8 quads = 1024 / 256 thr
        #pragma unroll
        for (int it = 0; it < 4; it++) {
            int idx = tid + it * 256;
            int r = idx >> 3, c4 = idx & 7;
            ar[it] = *reinterpret_cast<const float4*>(X + (size_t)(mBase + r) * INDIM + k0 + c4 * 4);
        }
    };
    auto stsA = [&](int st) {
        uint32_t* basep = smu + st * S1_BUFSZ;
        #pragma unroll
        for (int it = 0; it < 4; it++) {
            int idx = tid + it * 256;
            int r = idx >> 3, c4 = idx & 7;
            uint32_t* s = basep + r * PITCH + c4 * 2;
            s[0] = h2(ar[it].x, ar[it].y);
            s[1] = h2(ar[it].z, ar[it].w);
        }
    };
    auto cpB = [&](int k0, int st) {      // Wt fp16: 128 rows x 4 segs of 16B
        const uint32_t base = sb + st * (S1_BUFSZ * 4);
        #pragma unroll
        for (int it = 0; it < 2; it++) {
            int idx = tid + it * 256;
            int r = idx >> 2, s16 = idx & 3;
            CP16(base + (uint32_t)((S1_AROWS + r) * PITCH + s16 * 4) * 4,
                 Wt + (size_t)(fBase + r) * INDIM + k0 + s16 * 8);
        }
        CP_COMMIT();
    };

    float c[4][4][4];
    #pragma unroll
    for (int mt = 0; mt < 4; mt++)
        #pragma unroll
        for (int nt = 0; nt < 4; nt++)
            #pragma unroll
            for (int i = 0; i < 4; i++) c[mt][nt][i] = 0.0f;

    // Prologue: stages 0..2 staged; chunk 3's A in regs.
    cpB(0, 0); cpB(32, 1); cpB(64, 2);
    ldgA(0);  stsA(0);
    ldgA(32); stsA(1);
    ldgA(64); stsA(2);
    ldgA(96);

    const int NCHUNK = INDIM / 32;                // 16
    for (int cc = 0; cc < NCHUNK; cc++) {
        CP_WAIT2();
        __syncthreads();
        const int j = cc + 3;
        if (j < NCHUNK) { stsA(j & 3); cpB(j * 32, j & 3); }
        if (cc + 4 < NCHUNK) ldgA((cc + 4) * 32);
        chunk_mma_ldm<S1_AROWS>(sb + (cc & 3) * (S1_BUFSZ * 4), c, wr * 64, wc * 32, lid);
    }

    // Epilogue: bias + relu, write transposed HT[b][f][m] as fp16
    const int batch = mBase >> 8;
    __half* dst = HT + (size_t)batch * OUTDIM * N_;
    const int mloc = (mBase & 255) + wr * 64;
    #pragma unroll
    for (int mt = 0; mt < 4; mt++) {
        int m0 = mloc + mt * 16 + gid;
        #pragma unroll
        for (int nt = 0; nt < 4; nt++) {
            int f0 = fBase + wc * 32 + nt * 8 + tig * 2;
            float b0 = bias[f0], b1 = bias[f0 + 1];
            dst[(size_t)f0 * N_ + m0]           = __float2half_rn(fmaxf(c[mt][nt][0] + b0, 0.0f));
            dst[(size_t)(f0 + 1) * N_ + m0]     = __float2half_rn(fmaxf(c[mt][nt][1] + b1, 0.0f));
            dst[(size_t)f0 * N_ + m0 + 8]       = __float2half_rn(fmaxf(c[mt][nt][2] + b0, 0.0f));
            dst[(size_t)(f0 + 1) * N_ + m0 + 8] = __float2half_rn(fmaxf(c[mt][nt][3] + b1, 0.0f));
        }
    }
}

// ---------------------------------------------------------------------------
// Stage 2: out[b,n,k*64+d] = sum_m adj[b,k,n,m] * HT[b][k*64+d][m]
// CTA 128(n) x 64(d), 4 warps, warp tile 64x32. 8 m-chunks, 4-stage pipe.
// A(adj fp32): LDG -> (next iter) cvt+STS ; B(HT fp16): cp.async.
// (unchanged from R12)
// ---------------------------------------------------------------------------
__global__ __launch_bounds__(128) void s2_aggregate_mma(
    const float* __restrict__ adj, const __half* __restrict__ HT,
    float* __restrict__ out)
{
    extern __shared__ uint32_t smu2[];
    const uint32_t sb = smem_u32(smu2);

    const int tid = threadIdx.x;
    const int warpId = tid >> 5, lid = tid & 31;
    const int gid = lid >> 2, tig = lid & 3;
    const int wr = warpId & 1;            // n: 2 warps * 64
    const int wc = warpId >> 1;           // d: 2 warps * 32
    const int nBase = blockIdx.x * 128;
    const int kslot = blockIdx.y;
    const int bIdx  = blockIdx.z;

    const float*  A  = adj + (size_t)(bIdx * KSLOT + kslot) * N_ * N_;
    const __half* Bp = HT + ((size_t)bIdx * OUTDIM + kslot * DKDIM) * N_;

    float4 ar[8];

    auto ldgA = [&](int m0) {
        #pragma unroll
        for (int it = 0; it < 8; it++) {
            int idx = tid + it * 128;
            int r = idx >> 3, c4 = idx & 7;
            ar[it] = *reinterpret_cast<const float4*>(A + (size_t)(nBase + r) * N_ + m0 + c4 * 4);
        }
    };
    auto stsA = [&](int st) {
        uint32_t* basep = smu2 + st * S2_BUFSZ;
        #pragma unroll
        for (int it = 0; it < 8; it++) {
            int idx = tid + it * 128;
            int r = idx >> 3, c4 = idx & 7;
            uint32_t* s = basep + r * PITCH + c4 * 2;
            s[0] = h2(ar[it].x, ar[it].y);
            s[1] = h2(ar[it].z, ar[it].w);
        }
    };
    auto cpB = [&](int m0, int st) {      // HT fp16: 64 rows x 4 segs of 16B
        const uint32_t base = sb + st * (S2_BUFSZ * 4);
        #pragma unroll
        for (int it = 0; it < 2; it++) {
            int idx = tid + it * 128;
            int r = idx >> 2, s16 = idx & 3;
            CP16(base + (uint32_t)((S2_AROWS + r) * PITCH + s16 * 4) * 4,
                 Bp + (size_t)r * N_ + m0 + s16 * 8);
        }
        CP_COMMIT();
    };

    float c[4][4][4];
    #pragma unroll
    for (int mt = 0; mt < 4; mt++)
        #pragma unroll
        for (int nt = 0; nt < 4; nt++)
            #pragma unroll
            for (int i = 0; i < 4; i++) c[mt][nt][i] = 0.0f;

    // Prologue
    cpB(0, 0); cpB(32, 1); cpB(64, 2);
    ldgA(0);  stsA(0);
    ldgA(32); stsA(1);
    ldgA(64); stsA(2);
    ldgA(96);

    const int NCHUNK = N_ / 32;                   // 8
    for (int cc = 0; cc < NCHUNK; cc++) {
        CP_WAIT2();
        __syncthreads();
        const int j = cc + 3;
        if (j < NCHUNK) { stsA(j & 3); cpB(j * 32, j & 3); }
        if (cc + 4 < NCHUNK) ldgA((cc + 4) * 32);
        chunk_mma_ldm<S2_AROWS>(sb + (cc & 3) * (S2_BUFSZ * 4), c, wr * 64, wc * 32, lid);
    }

    // Epilogue: out[b][n][kslot*64 + d]  (fp32)
    float* dst = out + (size_t)bIdx * N_ * OUTDIM + kslot * DKDIM;
    #pragma unroll
    for (int mt = 0; mt < 4; mt++) {
        int n0 = nBase + wr * 64 + mt * 16 + gid;
        #pragma unroll
        for (int nt = 0; nt < 4; nt++) {
            int d0 = wc * 32 + nt * 8 + tig * 2;
            float2 v0 = make_float2(c[mt][nt][0], c[mt][nt][1]);
            float2 v1 = make_float2(c[mt][nt][2], c[mt][nt][3]);
            *reinterpret_cast<float2*>(dst + (size_t)n0 * OUTDIM + d0)       = v0;
            *reinterpret_cast<float2*>(dst + (size_t)(n0 + 8) * OUTDIM + d0) = v1;
        }
    }
}

// ---------------------------------------------------------------------------
extern "C" void kernel_launch(void* const* d_in, const int* in_sizes, int n_in,
                              void* d_out, int out_size)
{
    const float* node_feats = (const float*)d_in[0];  // (64,256,512)
    const float* adj        = (const float*)d_in[1];  // (64,8,256,256)
    const float* weight     = (const float*)d_in[2];  // (512,512)
    const float* bias       = (const float*)d_in[3];  // (512,)
    float* out = (float*)d_out;

    __half *HT, *WT;
    cudaGetSymbolAddress((void**)&HT, g_ht_h);
    cudaGetSymbolAddress((void**)&WT, g_wt_h);

    cudaFuncSetAttribute(s1_linear_mma, cudaFuncAttributeMaxDynamicSharedMemorySize, S1_DYN);
    cudaFuncSetAttribute(s2_aggregate_mma, cudaFuncAttributeMaxDynamicSharedMemorySize, S2_DYN);

    wt_kernel<<<dim3(OUTDIM / 32, INDIM / 32), dim3(32, 8)>>>(weight, WT);
    s1_linear_mma<<<dim3(OUTDIM / 128, (B_ * N_) / 128), 256, S1_DYN>>>(node_feats, WT, bias, HT);
    s2_aggregate_mma<<<dim3(N_ / 128, KSLOT, B_), 128, S2_DYN>>>(adj, HT, out);
}

// round 16
// speedup vs baseline: 1.2069x; 1.2069x over previous
#include <cuda_runtime.h>
#include <cuda_fp16.h>
#include <cstdint>

#define B_     64
#define N_     256
#define INDIM  512
#define OUTDIM 512
#define KSLOT  8
#define DKDIM  64

// Scratch: HT fp16 [b][feature][m], Wt fp16 [out][in], XH fp16 [m][k]
__device__ __half g_ht_h[(size_t)B_ * OUTDIM * N_];
__device__ __half g_wt_h[OUTDIM * INDIM];
__device__ __half g_xh_h[(size_t)B_ * N_ * INDIM];

// ---------------------------------------------------------------------------
__device__ __forceinline__ uint32_t h2(float x, float y) {
    __half2 t = __floats2half2_rn(x, y);      // .x = low halfword
    return *reinterpret_cast<uint32_t*>(&t);
}

__device__ __forceinline__ void mma_fp16(float c[4], const uint32_t a[4], const uint32_t b[2]) {
    asm volatile(
        "mma.sync.aligned.m16n8k16.row.col.f32.f16.f16.f32 "
        "{%0,%1,%2,%3}, {%4,%5,%6,%7}, {%8,%9}, {%0,%1,%2,%3};"
        : "+f"(c[0]), "+f"(c[1]), "+f"(c[2]), "+f"(c[3])
        : "r"(a[0]), "r"(a[1]), "r"(a[2]), "r"(a[3]), "r"(b[0]), "r"(b[1]));
}

__device__ __forceinline__ void ldm4(uint32_t& r0, uint32_t& r1, uint32_t& r2, uint32_t& r3,
                                     uint32_t addr) {
    asm volatile("ldmatrix.sync.aligned.m8n8.x4.shared.b16 {%0,%1,%2,%3}, [%4];"
                 : "=r"(r0), "=r"(r1), "=r"(r2), "=r"(r3) : "r"(addr));
}

__device__ __forceinline__ uint32_t smem_u32(const void* p) {
    uint32_t a;
    asm("{ .reg .u64 t; cvta.to.shared.u64 t, %1; cvt.u32.u64 %0, t; }" : "=r"(a) : "l"(p));
    return a;
}

#define CP16(dst_u32, src_ptr) \
    asm volatile("cp.async.cg.shared.global [%0], [%1], 16;" :: "r"(dst_u32), "l"(src_ptr))
#define CP_COMMIT() asm volatile("cp.async.commit_group;" ::: "memory")
#define CP_WAIT2()  asm volatile("cp.async.wait_group 2;" ::: "memory")

// Row = 32 fp16 k-elements = 16 uint32 + 4 pad -> PITCH 20 uint32 (80 B).
// ldmatrix phase: 8 rows x 16B, start banks 20r mod 32 = perfect permutation.
#define PITCH   20
#define BUFROWS 192                       // A: rows 0..127, B: rows 128..191
#define BUFSZ   (BUFROWS * PITCH)         // uint32 per stage
#define NSTAGE  4
#define S_DYN   (NSTAGE * BUFSZ * 4)      // 61440 B

// ---------------------------------------------------------------------------
// Kernel 0 (fused prep):
//   CTAs [0,256):    Wt[n][k] = (half)W[k][n]
//   CTAs [256,1280): XH = (half)X   (8M elems, 32/thread)
// ---------------------------------------------------------------------------
__global__ __launch_bounds__(256) void prep_kernel(
    const float* __restrict__ W, const float* __restrict__ X,
    __half* __restrict__ Wt, __half* __restrict__ XH)
{
    const int tid = threadIdx.x;
    if (blockIdx.x < 256) {
        __shared__ float t[32][33];
        const int tx = tid & 31, ty = tid >> 5;
        const int bx = (blockIdx.x & 15) * 32;   // out (n)
        const int by = (blockIdx.x >> 4) * 32;   // in  (k)
        #pragma unroll
        for (int i = 0; i < 4; i++)
            t[ty + i * 8][tx] = W[(size_t)(by + ty + i * 8) * OUTDIM + bx + tx];
        __syncthreads();
        #pragma unroll
        for (int i = 0; i < 4; i++)
            Wt[(size_t)(bx + ty + i * 8) * INDIM + by + tx] =
                __float2half_rn(t[tx][ty + i * 8]);
    } else {
        // X convert: 1024 CTAs x 256 threads x 32 elems
        const size_t base = ((size_t)(blockIdx.x - 256) * 256 + tid) * 32;
        #pragma unroll
        for (int j = 0; j < 4; j++) {
            size_t off = base + (size_t)j * 8;
            float4 v0 = *reinterpret_cast<const float4*>(X + off);
            float4 v1 = *reinterpret_cast<const float4*>(X + off + 4);
            uint4 o;
            o.x = h2(v0.x, v0.y); o.y = h2(v0.z, v0.w);
            o.z = h2(v1.x, v1.y); o.w = h2(v1.z, v1.w);
            *reinterpret_cast<uint4*>(XH + off) = o;
        }
    }
}

// ---------------------------------------------------------------------------
// Fragment compute over one resident stage (k=32 -> 2 k16 steps), ldmatrix.
// Warp tile 64(m) x 32(n). B rows start at 128.
// ---------------------------------------------------------------------------
__device__ __forceinline__ void chunk_mma_ldm(
    uint32_t sbase, float c[4][4][4], int rowA0, int rowB0, int lane)
{
    const int lr = lane & 15;
    const int lc = lane >> 4;
    #pragma unroll
    for (int ks = 0; ks < 2; ks++) {
        const uint32_t segoff = (uint32_t)(ks * 2 + lc) * 16u;   // bytes
        uint32_t afr[4][4];
        #pragma unroll
        for (int mt = 0; mt < 4; mt++) {
            uint32_t addr = sbase + (uint32_t)(rowA0 + mt * 16 + lr) * (PITCH * 4) + segoff;
            ldm4(afr[mt][0], afr[mt][1], afr[mt][2], afr[mt][3], addr);
        }
        uint32_t bfr[4][2];
        #pragma unroll
        for (int p = 0; p < 2; p++) {
            uint32_t addr = sbase + (uint32_t)(128 + rowB0 + p * 16 + lr) * (PITCH * 4) + segoff;
            uint32_t r0, r1, r2, r3;
            ldm4(r0, r1, r2, r3, addr);
            bfr[2 * p][0] = r0; bfr[2 * p + 1][0] = r1;
            bfr[2 * p][1] = r2; bfr[2 * p + 1][1] = r3;
        }
        #pragma unroll
        for (int mt = 0; mt < 4; mt++)
            #pragma unroll
            for (int nt = 0; nt < 4; nt++)
                mma_fp16(c[mt][nt], afr[mt], bfr[nt]);
    }
}

// ---------------------------------------------------------------------------
// Stage 1: HT[b][f][m] = (half) relu( XH @ Wt^T + bias )
// CTA 128(m) x 64(f), 4 warps, warp tile 64x32. 16 k-chunks, 4-stage pipe.
// BOTH operands fp16 via cp.async. A commit EVERY iteration (empty groups in
// the tail) keeps the wait_group-2 invariant: consumed stage always complete.
// ---------------------------------------------------------------------------
__global__ __launch_bounds__(128) void s1_linear_mma(
    const __half* __restrict__ XH, const __half* __restrict__ Wt,
    const float* __restrict__ bias, __half* __restrict__ HT)
{
    extern __shared__ uint32_t smu[];
    const uint32_t sb = smem_u32(smu);

    const int tid = threadIdx.x;
    const int warpId = tid >> 5, lid = tid & 31;
    const int gid = lid >> 2, tig = lid & 3;
    const int wr = warpId & 1;            // m: 2 warps * 64
    const int wc = warpId >> 1;           // f: 2 warps * 32
    const int mBase = blockIdx.y * 128;
    const int fBase = blockIdx.x * 64;

    auto cpStage = [&](int k0, int st) {
        const uint32_t base = sb + st * (BUFSZ * 4);
        // A(XH): 128 rows x 4 segs of 16B = 512 chunks / 128 thr
        #pragma unroll
        for (int it = 0; it < 4; it++) {
            int idx = tid + it * 128;
            int r = idx >> 2, s16 = idx & 3;
            CP16(base + (uint32_t)(r * PITCH + s16 * 4) * 4,
                 XH + (size_t)(mBase + r) * INDIM + k0 + s16 * 8);
        }
        // B(Wt): 64 rows x 4 segs of 16B = 256 chunks
        #pragma unroll
        for (int it = 0; it < 2; it++) {
            int idx = tid + it * 128;
            int r = idx >> 2, s16 = idx & 3;
            CP16(base + (uint32_t)((128 + r) * PITCH + s16 * 4) * 4,
                 Wt + (size_t)(fBase + r) * INDIM + k0 + s16 * 8);
        }
        CP_COMMIT();
    };

    float c[4][4][4];
    #pragma unroll
    for (int mt = 0; mt < 4; mt++)
        #pragma unroll
        for (int nt = 0; nt < 4; nt++)
            #pragma unroll
            for (int i = 0; i < 4; i++) c[mt][nt][i] = 0.0f;

    cpStage(0, 0); cpStage(32, 1); cpStage(64, 2);

    const int NCHUNK = INDIM / 32;                // 16
    for (int cc = 0; cc < NCHUNK; cc++) {
        CP_WAIT2();
        __syncthreads();
        const int j = cc + 3;
        if (j < NCHUNK) cpStage(j * 32, j & 3);
        else            CP_COMMIT();              // empty group: keep invariant
        chunk_mma_ldm(sb + (cc & 3) * (BUFSZ * 4), c, wr * 64, wc * 32, lid);
    }

    // Epilogue: bias + relu, write transposed HT[b][f][m] as fp16
    const int batch = mBase >> 8;
    __half* dst = HT + (size_t)batch * OUTDIM * N_;
    const int mloc = (mBase & 255) + wr * 64;
    #pragma unroll
    for (int mt = 0; mt < 4; mt++) {
        int m0 = mloc + mt * 16 + gid;
        #pragma unroll
        for (int nt = 0; nt < 4; nt++) {
            int f0 = fBase + wc * 32 + nt * 8 + tig * 2;
            float b0 = bias[f0], b1 = bias[f0 + 1];
            dst[(size_t)f0 * N_ + m0]           = __float2half_rn(fmaxf(c[mt][nt][0] + b0, 0.0f));
            dst[(size_t)(f0 + 1) * N_ + m0]     = __float2half_rn(fmaxf(c[mt][nt][1] + b1, 0.0f));
            dst[(size_t)f0 * N_ + m0 + 8]       = __float2half_rn(fmaxf(c[mt][nt][2] + b0, 0.0f));
            dst[(size_t)(f0 + 1) * N_ + m0 + 8] = __float2half_rn(fmaxf(c[mt][nt][3] + b1, 0.0f));
        }
    }
}

// ---------------------------------------------------------------------------
// Stage 2: out[b,n,k*64+d] = sum_m adj[b,k,n,m] * HT[b][k*64+d][m]
// CTA 128(n) x 64(d), 4 warps, warp tile 64x32. 8 m-chunks, 4-stage pipe.
// A(adj fp32): LDG -> (next iter) cvt+STS ; B(HT fp16): cp.async.
// Commit every iteration (empty tail groups) — same invariant fix.
// ---------------------------------------------------------------------------
__global__ __launch_bounds__(128) void s2_aggregate_mma(
    const float* __restrict__ adj, const __half* __restrict__ HT,
    float* __restrict__ out)
{
    extern __shared__ uint32_t smu2[];
    const uint32_t sb = smem_u32(smu2);

    const int tid = threadIdx.x;
    const int warpId = tid >> 5, lid = tid & 31;
    const int gid = lid >> 2, tig = lid & 3;
    const int wr = warpId & 1;            // n: 2 warps * 64
    const int wc = warpId >> 1;           // d: 2 warps * 32
    const int nBase = blockIdx.x * 128;
    const int kslot = blockIdx.y;
    const int bIdx  = blockIdx.z;

    const float*  A  = adj + (size_t)(bIdx * KSLOT + kslot) * N_ * N_;
    const __half* Bp = HT + ((size_t)bIdx * OUTDIM + kslot * DKDIM) * N_;

    float4 ar[8];

    auto ldgA = [&](int m0) {
        #pragma unroll
        for (int it = 0; it < 8; it++) {
            int idx = tid + it * 128;
            int r = idx >> 3, c4 = idx & 7;
            ar[it] = *reinterpret_cast<const float4*>(A + (size_t)(nBase + r) * N_ + m0 + c4 * 4);
        }
    };
    auto stsA = [&](int st) {
        uint32_t* basep = smu2 + st * BUFSZ;
        #pragma unroll
        for (int it = 0; it < 8; it++) {
            int idx = tid + it * 128;
            int r = idx >> 3, c4 = idx & 7;
            uint32_t* s = basep + r * PITCH + c4 * 2;
            s[0] = h2(ar[it].x, ar[it].y);
            s[1] = h2(ar[it].z, ar[it].w);
        }
    };
    auto cpB = [&](int m0, int st) {      // HT fp16: 64 rows x 4 segs of 16B
        const uint32_t base = sb + st * (BUFSZ * 4);
        #pragma unroll
        for (int it = 0; it < 2; it++) {
            int idx = tid + it * 128;
            int r = idx >> 2, s16 = idx & 3;
            CP16(base + (uint32_t)((128 + r) * PITCH + s16 * 4) * 4,
                 Bp + (size_t)r * N_ + m0 + s16 * 8);
        }
        CP_COMMIT();
    };

    float c[4][4][4];
    #pragma unroll
    for (int mt = 0; mt < 4; mt++)
        #pragma unroll
        for (int nt = 0; nt < 4; nt++)
            #pragma unroll
            for (int i = 0; i < 4; i++) c[mt][nt][i] = 0.0f;

    // Prologue: stages 0..2 staged; chunk 3's A in regs.
    cpB(0, 0); cpB(32, 1); cpB(64, 2);
    ldgA(0);  stsA(0);
    ldgA(32); stsA(1);
    ldgA(64); stsA(2);
    ldgA(96);

    const int NCHUNK = N_ / 32;                   // 8
    for (int cc = 0; cc < NCHUNK; cc++) {
        CP_WAIT2();
        __syncthreads();
        const int j = cc + 3;
        if (j < NCHUNK) { stsA(j & 3); cpB(j * 32, j & 3); }
        else            CP_COMMIT();              // empty group: keep invariant
        if (cc + 4 < NCHUNK) ldgA((cc + 4) * 32);
        chunk_mma_ldm(sb + (cc & 3) * (BUFSZ * 4), c, wr * 64, wc * 32, lid);
    }

    // Epilogue: out[b][n][kslot*64 + d]  (fp32)
    float* dst = out + (size_t)bIdx * N_ * OUTDIM + kslot * DKDIM;
    #pragma unroll
    for (int mt = 0; mt < 4; mt++) {
        int n0 = nBase + wr * 64 + mt * 16 + gid;
        #pragma unroll
        for (int nt = 0; nt < 4; nt++) {
            int d0 = wc * 32 + nt * 8 + tig * 2;
            float2 v0 = make_float2(c[mt][nt][0], c[mt][nt][1]);
            float2 v1 = make_float2(c[mt][nt][2], c[mt][nt][3]);
            *reinterpret_cast<float2*>(dst + (size_t)n0 * OUTDIM + d0)       = v0;
            *reinterpret_cast<float2*>(dst + (size_t)(n0 + 8) * OUTDIM + d0) = v1;
        }
    }
}

// ---------------------------------------------------------------------------
extern "C" void kernel_launch(void* const* d_in, const int* in_sizes, int n_in,
                              void* d_out, int out_size)
{
    const float* node_feats = (const float*)d_in[0];  // (64,256,512)
    const float* adj        = (const float*)d_in[1];  // (64,8,256,256)
    const float* weight     = (const float*)d_in[2];  // (512,512)
    const float* bias       = (const float*)d_in[3];  // (512,)
    float* out = (float*)d_out;

    __half *HT, *WT, *XH;
    cudaGetSymbolAddress((void**)&HT, g_ht_h);
    cudaGetSymbolAddress((void**)&WT, g_wt_h);
    cudaGetSymbolAddress((void**)&XH, g_xh_h);

    cudaFuncSetAttribute(s1_linear_mma, cudaFuncAttributeMaxDynamicSharedMemorySize, S_DYN);
    cudaFuncSetAttribute(s2_aggregate_mma, cudaFuncAttributeMaxDynamicSharedMemorySize, S_DYN);

    prep_kernel<<<1280, 256>>>(weight, node_feats, WT, XH);
    s1_linear_mma<<<dim3(OUTDIM / 64, (B_ * N_) / 128), 128, S_DYN>>>(XH, WT, bias, HT);
    s2_aggregate_mma<<<dim3(N_ / 128, KSLOT, B_), 128, S_DYN>>>(adj, HT, out);
}

// round 17
// speedup vs baseline: 1.2591x; 1.0432x over previous
#include <cuda_runtime.h>
#include <cuda_fp16.h>
#include <cstdint>

#define B_     64
#define N_     256
#define INDIM  512
#define OUTDIM 512
#define KSLOT  8
#define DKDIM  64

// Scratch: Wt fp16 [out][in], XH fp16 [b][m][k]
__device__ __half g_wt_h[OUTDIM * INDIM];
__device__ __half g_xh_h[(size_t)B_ * N_ * INDIM];

// ---------------------------------------------------------------------------
__device__ __forceinline__ uint32_t h2(float x, float y) {
    __half2 t = __floats2half2_rn(x, y);      // .x = low halfword
    return *reinterpret_cast<uint32_t*>(&t);
}

__device__ __forceinline__ void mma_fp16(float c[4], const uint32_t a[4], const uint32_t b[2]) {
    asm volatile(
        "mma.sync.aligned.m16n8k16.row.col.f32.f16.f16.f32 "
        "{%0,%1,%2,%3}, {%4,%5,%6,%7}, {%8,%9}, {%0,%1,%2,%3};"
        : "+f"(c[0]), "+f"(c[1]), "+f"(c[2]), "+f"(c[3])
        : "r"(a[0]), "r"(a[1]), "r"(a[2]), "r"(a[3]), "r"(b[0]), "r"(b[1]));
}

__device__ __forceinline__ void ldm4(uint32_t& r0, uint32_t& r1, uint32_t& r2, uint32_t& r3,
                                     uint32_t addr) {
    asm volatile("ldmatrix.sync.aligned.m8n8.x4.shared.b16 {%0,%1,%2,%3}, [%4];"
                 : "=r"(r0), "=r"(r1), "=r"(r2), "=r"(r3) : "r"(addr));
}

__device__ __forceinline__ uint32_t smem_u32(const void* p) {
    uint32_t a;
    asm("{ .reg .u64 t; cvta.to.shared.u64 t, %1; cvt.u32.u64 %0, t; }" : "=r"(a) : "l"(p));
    return a;
}

#define CP16(dst_u32, src_ptr) \
    asm volatile("cp.async.cg.shared.global [%0], [%1], 16;" :: "r"(dst_u32), "l"(src_ptr))
#define CP_COMMIT() asm volatile("cp.async.commit_group;" ::: "memory")
#define CP_WAIT1()  asm volatile("cp.async.wait_group 1;" ::: "memory")
#define CP_WAIT0()  asm volatile("cp.async.wait_group 0;" ::: "memory")

// Operand rows: 32 fp16 k-elems = 16 u32 + 4 pad -> pitch 20 u32 (80 B).
// ldmatrix phase: 8 rows x 16B, start banks 20r mod 32 = perfect permutation.
#define PITCH 20
// Fused-kernel smem: 3 pipeline stages (A rows 0..255, B rows 256..319) + Hk.
#define STG_ROWS   320
#define STG_U32    (STG_ROWS * PITCH)        // 6400 u32 = 25600 B
#define NST        3
#define HK_PITCH   132                        // u32 per d-row (256 halves + 4 pad)
#define HK_OFF_U32 (NST * STG_U32)            // 19200
#define S_DYN      ((NST * STG_U32 + 64 * HK_PITCH) * 4)   // 110592 B

// ---------------------------------------------------------------------------
// Prep: CTAs [0,256): Wt[n][k] = (half)W[k][n]
//       CTAs [256,4352): XH = (half)X, fully coalesced (8 contiguous/thread)
// ---------------------------------------------------------------------------
__global__ __launch_bounds__(256) void prep_kernel(
    const float* __restrict__ W, const float* __restrict__ X,
    __half* __restrict__ Wt, __half* __restrict__ XH)
{
    const int tid = threadIdx.x;
    if (blockIdx.x < 256) {
        __shared__ float t[32][33];
        const int tx = tid & 31, ty = tid >> 5;
        const int bx = (blockIdx.x & 15) * 32;   // out (n)
        const int by = (blockIdx.x >> 4) * 32;   // in  (k)
        #pragma unroll
        for (int i = 0; i < 4; i++)
            t[ty + i * 8][tx] = W[(size_t)(by + ty + i * 8) * OUTDIM + bx + tx];
        __syncthreads();
        #pragma unroll
        for (int i = 0; i < 4; i++)
            Wt[(size_t)(bx + ty + i * 8) * INDIM + by + tx] =
                __float2half_rn(t[tx][ty + i * 8]);
    } else {
        // 4096 CTAs x 256 threads x 8 contiguous elems — coalesced
        const size_t off = ((size_t)(blockIdx.x - 256) * 256 + tid) * 8;
        float4 v0 = *reinterpret_cast<const float4*>(X + off);
        float4 v1 = *reinterpret_cast<const float4*>(X + off + 4);
        uint4 o;
        o.x = h2(v0.x, v0.y); o.y = h2(v0.z, v0.w);
        o.z = h2(v1.x, v1.y); o.w = h2(v1.z, v1.w);
        *reinterpret_cast<uint4*>(XH + off) = o;
    }
}

// ---------------------------------------------------------------------------
// Fused kernel: one CTA per (kslot, b). 256 threads, 8 warps (4 wr x 2 wc),
// warp tile 64x32.
//  Phase 1: Hk[256 m][64 f] = relu(XH_b @ Wt[kslot*64..][.]^T + bias) -> smem
//  Phase 2: out[b, n, kslot*64+d] = adj_bk[n][m] @ Hk[m][d]
// ---------------------------------------------------------------------------
__global__ __launch_bounds__(256) void fused_kernel(
    const __half* __restrict__ XH, const __half* __restrict__ Wt,
    const float* __restrict__ bias, const float* __restrict__ adj,
    float* __restrict__ out)
{
    extern __shared__ uint32_t smu[];
    const uint32_t sb = smem_u32(smu);

    const int tid = threadIdx.x;
    const int warpId = tid >> 5, lid = tid & 31;
    const int gid = lid >> 2, tig = lid & 3;
    const int lr = lid & 15, lc = lid >> 4;
    const int wr = warpId & 3;            // rows: 4 warps * 64 (m or n)
    const int wc = warpId >> 2;           // cols: 2 warps * 32 (f or d)
    const int kslot = blockIdx.x;
    const int bIdx  = blockIdx.y;

    const __half* XHb = XH + (size_t)bIdx * N_ * INDIM;
    const __half* Wts = Wt + (size_t)(kslot * DKDIM) * INDIM;

    float c[4][4][4];
    #pragma unroll
    for (int mt = 0; mt < 4; mt++)
        #pragma unroll
        for (int nt = 0; nt < 4; nt++)
            #pragma unroll
            for (int i = 0; i < 4; i++) c[mt][nt][i] = 0.0f;

    // ---------------- Phase 1: 16 k-chunks, 3-stage cp.async -------------
    auto cpStage1 = [&](int k0, int st) {
        const uint32_t base = sb + st * (STG_U32 * 4);
        #pragma unroll
        for (int it = 0; it < 4; it++) {          // A(XH): 256 rows x 4 segs
            int idx = tid + it * 256;
            int r = idx >> 2, s16 = idx & 3;
            CP16(base + (uint32_t)(r * PITCH + s16 * 4) * 4,
                 XHb + (size_t)r * INDIM + k0 + s16 * 8);
        }
        {                                          // B(Wt slice): 64 rows x 4
            int r = tid >> 2, s16 = tid & 3;
            CP16(base + (uint32_t)((256 + r) * PITCH + s16 * 4) * 4,
                 Wts + (size_t)r * INDIM + k0 + s16 * 8);
        }
        CP_COMMIT();
    };

    cpStage1(0, 0); cpStage1(32, 1);

    const int NCH1 = INDIM / 32;                  // 16
    for (int cc = 0; cc < NCH1; cc++) {
        CP_WAIT1();
        __syncthreads();                          // also guards stage reuse
        const int j = cc + 2;
        if (j < NCH1) cpStage1(j * 32, j % 3);
        else          CP_COMMIT();                // empty group: keep invariant
        // compute on stage cc%3
        const uint32_t sbase = sb + (cc % 3) * (STG_U32 * 4);
        #pragma unroll
        for (int ks = 0; ks < 2; ks++) {
            const uint32_t segoff = (uint32_t)(ks * 2 + lc) * 16u;
            uint32_t afr[4][4];
            #pragma unroll
            for (int mt = 0; mt < 4; mt++) {
                uint32_t addr = sbase + (uint32_t)(wr * 64 + mt * 16 + lr) * (PITCH * 4) + segoff;
                ldm4(afr[mt][0], afr[mt][1], afr[mt][2], afr[mt][3], addr);
            }
            uint32_t bfr[4][2];
            #pragma unroll
            for (int p = 0; p < 2; p++) {
                uint32_t addr = sbase + (uint32_t)(256 + wc * 32 + p * 16 + lr) * (PITCH * 4) + segoff;
                uint32_t r0, r1, r2, r3;
                ldm4(r0, r1, r2, r3, addr);
                bfr[2 * p][0] = r0; bfr[2 * p + 1][0] = r1;
                bfr[2 * p][1] = r2; bfr[2 * p + 1][1] = r3;
            }
            #pragma unroll
            for (int mt = 0; mt < 4; mt++)
                #pragma unroll
                for (int nt = 0; nt < 4; nt++)
                    mma_fp16(c[mt][nt], afr[mt], bfr[nt]);
        }
    }
    CP_WAIT0();
    __syncthreads();

    // Phase-1 epilogue: bias + relu -> Hk smem [d][m] (fp16, pitch 264 halves)
    {
        __half* hk = reinterpret_cast<__half*>(smu + HK_OFF_U32);
        #pragma unroll
        for (int mt = 0; mt < 4; mt++) {
            int m0 = wr * 64 + mt * 16 + gid;
            #pragma unroll
            for (int nt = 0; nt < 4; nt++) {
                int d0 = wc * 32 + nt * 8 + tig * 2;
                float b0 = bias[kslot * DKDIM + d0];
                float b1 = bias[kslot * DKDIM + d0 + 1];
                hk[(size_t)d0 * (HK_PITCH * 2) + m0]           = __float2half_rn(fmaxf(c[mt][nt][0] + b0, 0.0f));
                hk[(size_t)(d0 + 1) * (HK_PITCH * 2) + m0]     = __float2half_rn(fmaxf(c[mt][nt][1] + b1, 0.0f));
                hk[(size_t)d0 * (HK_PITCH * 2) + m0 + 8]       = __float2half_rn(fmaxf(c[mt][nt][2] + b0, 0.0f));
                hk[(size_t)(d0 + 1) * (HK_PITCH * 2) + m0 + 8] = __float2half_rn(fmaxf(c[mt][nt][3] + b1, 0.0f));
            }
        }
    }
    __syncthreads();

    // ---------------- Phase 2: 8 m-chunks, 2-stage LDG/STS ----------------
    #pragma unroll
    for (int mt = 0; mt < 4; mt++)
        #pragma unroll
        for (int nt = 0; nt < 4; nt++)
            #pragma unroll
            for (int i = 0; i < 4; i++) c[mt][nt][i] = 0.0f;

    const float* A = adj + (size_t)(bIdx * KSLOT + kslot) * N_ * N_;
    float4 ar[8];

    auto ldgA = [&](int m0) {                     // 256 rows x 8 quads / 256 thr
        #pragma unroll
        for (int it = 0; it < 8; it++) {
            int idx = tid + it * 256;
            int r = idx >> 3, c4 = idx & 7;
            ar[it] = *reinterpret_cast<const float4*>(A + (size_t)r * N_ + m0 + c4 * 4);
        }
    };
    auto stsA = [&](int st) {
        uint32_t* basep = smu + st * STG_U32;
        #pragma unroll
        for (int it = 0; it < 8; it++) {
            int idx = tid + it * 256;
            int r = idx >> 3, c4 = idx & 7;
            uint32_t* s = basep + r * PITCH + c4 * 2;
            s[0] = h2(ar[it].x, ar[it].y);
            s[1] = h2(ar[it].z, ar[it].w);
        }
    };

    ldgA(0); stsA(0);
    __syncthreads();

    const int NCH2 = N_ / 32;                     // 8
    for (int cc = 0; cc < NCH2; cc++) {
        const bool hasNext = (cc + 1 < NCH2);
        if (hasNext) ldgA((cc + 1) * 32);
        // compute on stage cc&1; B from Hk (static smem)
        const uint32_t sbase = sb + (cc & 1) * (STG_U32 * 4);
        const uint32_t hkbase = sb + HK_OFF_U32 * 4 + (uint32_t)cc * 64u;
        #pragma unroll
        for (int ks = 0; ks < 2; ks++) {
            const uint32_t segoff = (uint32_t)(ks * 2 + lc) * 16u;
            uint32_t afr[4][4];
            #pragma unroll
            for (int mt = 0; mt < 4; mt++) {
                uint32_t addr = sbase + (uint32_t)(wr * 64 + mt * 16 + lr) * (PITCH * 4) + segoff;
                ldm4(afr[mt][0], afr[mt][1], afr[mt][2], afr[mt][3], addr);
            }
            uint32_t bfr[4][2];
            #pragma unroll
            for (int p = 0; p < 2; p++) {
                uint32_t addr = hkbase + (uint32_t)(wc * 32 + p * 16 + lr) * (HK_PITCH * 4) + segoff;
                uint32_t r0, r1, r2, r3;
                ldm4(r0, r1, r2, r3, addr);
                bfr[2 * p][0] = r0; bfr[2 * p + 1][0] = r1;
                bfr[2 * p][1] = r2; bfr[2 * p + 1][1] = r3;
            }
            #pragma unroll
            for (int mt = 0; mt < 4; mt++)
                #pragma unroll
                for (int nt = 0; nt < 4; nt++)
                    mma_fp16(c[mt][nt], afr[mt], bfr[nt]);
        }
        if (hasNext) {
            stsA((cc + 1) & 1);
            __syncthreads();
        }
    }

    // Phase-2 epilogue: out[b][n][kslot*64 + d] (fp32)
    float* dst = out + (size_t)bIdx * N_ * OUTDIM + kslot * DKDIM;
    #pragma unroll
    for (int mt = 0; mt < 4; mt++) {
        int n0 = wr * 64 + mt * 16 + gid;
        #pragma unroll
        for (int nt = 0; nt < 4; nt++) {
            int d0 = wc * 32 + nt * 8 + tig * 2;
            float2 v0 = make_float2(c[mt][nt][0], c[mt][nt][1]);
            float2 v1 = make_float2(c[mt][nt][2], c[mt][nt][3]);
            *reinterpret_cast<float2*>(dst + (size_t)n0 * OUTDIM + d0)       = v0;
            *reinterpret_cast<float2*>(dst + (size_t)(n0 + 8) * OUTDIM + d0) = v1;
        }
    }
}

// ---------------------------------------------------------------------------
extern "C" void kernel_launch(void* const* d_in, const int* in_sizes, int n_in,
                              void* d_out, int out_size)
{
    const float* node_feats = (const float*)d_in[0];  // (64,256,512)
    const float* adj        = (const float*)d_in[1];  // (64,8,256,256)
    const float* weight     = (const float*)d_in[2];  // (512,512)
    const float* bias       = (const float*)d_in[3];  // (512,)
    float* out = (float*)d_out;

    __half *WT, *XH;
    cudaGetSymbolAddress((void**)&WT, g_wt_h);
    cudaGetSymbolAddress((void**)&XH, g_xh_h);

    cudaFuncSetAttribute(fused_kernel, cudaFuncAttributeMaxDynamicSharedMemorySize, S_DYN);

    prep_kernel<<<4352, 256>>>(weight, node_feats, WT, XH);
    fused_kernel<<<dim3(KSLOT, B_), 256, S_DYN>>>(XH, WT, bias, adj, out);
}